// round 9
// baseline (speedup 1.0000x reference)
#include <cuda_runtime.h>
#include <cuda_fp16.h>
#include <cstdint>

// (B, N, H, D) = (2, 4096, 8, 64)
#define BATCH 2
#define SEQ   4096
#define NH    8
#define HD    64
#define MODEL 512
#define BM    128            // query rows per CTA (4 warps x 32)
#define BN    64             // keys per tile
#define NTILES (SEQ / BN)    // 64
#define LS 0.180336879f      // 0.125 * log2(e): exp(s/8) = exp2(s*LS)
#define ONES2 0x3C003C00u    // half2(1.0, 1.0)

// Device scratch (no cudaMalloc allowed)
__device__ __align__(16) float  g_attn[(size_t)BATCH * SEQ * MODEL];
__device__ __align__(16) __half g_qh[(size_t)BATCH * NH * SEQ * HD];
__device__ __align__(16) __half g_kh[(size_t)BATCH * NH * SEQ * HD];
__device__ __align__(16) __half g_vh[(size_t)BATCH * NH * SEQ * HD];

// SMEM layout (bytes). Row pitch = 64 halfs + 8 pad = 144 B (conflict-free).
#define RPITCH 144
#define QS_B 0                       // 128 * 144 = 18432
#define KS_B 18432                   // 2 x (64*144 = 9216)
#define VS_B (KS_B + 2 * 9216)       // 36864
#define SMEM_BYTES (VS_B + 2 * 9216) // 55296

__device__ __forceinline__ uint32_t smem_u32(const void* p) {
    uint32_t a;
    asm("{ .reg .u64 t; cvta.to.shared.u64 t, %1; cvt.u32.u64 %0, t; }"
        : "=r"(a) : "l"(p));
    return a;
}
__device__ __forceinline__ float ex2(float x) {
    float r; asm("ex2.approx.ftz.f32 %0, %1;" : "=f"(r) : "f"(x)); return r;
}
__device__ __forceinline__ uint32_t ex2_h2(uint32_t x) {
    uint32_t r; asm("ex2.approx.f16x2 %0, %1;" : "=r"(r) : "r"(x)); return r;
}
__device__ __forceinline__ void cp_async16(uint32_t dst, const void* src) {
    asm volatile("cp.async.cg.shared.global [%0], [%1], 16;"
                 :: "r"(dst), "l"(src) : "memory");
}
#define CP_COMMIT() asm volatile("cp.async.commit_group;" ::: "memory")
#define CP_WAIT(n)  asm volatile("cp.async.wait_group %0;" :: "n"(n) : "memory")

__device__ __forceinline__ void ldsm_x4(uint32_t& r0, uint32_t& r1,
                                        uint32_t& r2, uint32_t& r3, uint32_t a) {
    asm volatile("ldmatrix.sync.aligned.m8n8.x4.shared.b16 {%0,%1,%2,%3}, [%4];"
                 : "=r"(r0), "=r"(r1), "=r"(r2), "=r"(r3) : "r"(a));
}
__device__ __forceinline__ void ldsm_x4_t(uint32_t& r0, uint32_t& r1,
                                          uint32_t& r2, uint32_t& r3, uint32_t a) {
    asm volatile("ldmatrix.sync.aligned.m8n8.x4.trans.shared.b16 {%0,%1,%2,%3}, [%4];"
                 : "=r"(r0), "=r"(r1), "=r"(r2), "=r"(r3) : "r"(a));
}
// fp32-accumulate (used for O and L)
__device__ __forceinline__ void mma_f16(float c[4], const uint32_t a[4],
                                        uint32_t b0, uint32_t b1) {
    asm volatile(
        "mma.sync.aligned.m16n8k16.row.col.f32.f16.f16.f32 "
        "{%0,%1,%2,%3}, {%4,%5,%6,%7}, {%8,%9}, {%0,%1,%2,%3};"
        : "+f"(c[0]), "+f"(c[1]), "+f"(c[2]), "+f"(c[3])
        : "r"(a[0]), "r"(a[1]), "r"(a[2]), "r"(a[3]), "r"(b0), "r"(b1));
}
// fp16-accumulate (used for S; D/C are 2 packed-half2 regs)
__device__ __forceinline__ void mma_f16h(uint32_t c[2], const uint32_t a[4],
                                         uint32_t b0, uint32_t b1) {
    asm volatile(
        "mma.sync.aligned.m16n8k16.row.col.f16.f16.f16.f16 "
        "{%0,%1}, {%2,%3,%4,%5}, {%6,%7}, {%0,%1};"
        : "+r"(c[0]), "+r"(c[1])
        : "r"(a[0]), "r"(a[1]), "r"(a[2]), "r"(a[3]), "r"(b0), "r"(b1));
}
__device__ __forceinline__ uint32_t h2pack(float a, float b) {
    __half2 h = __floats2half2_rn(a, b);
    return *reinterpret_cast<uint32_t*>(&h);
}

// ---------------------------------------------------------------------------
// Prolog: fp32 [b,n,h*d] -> fp16 [b,h,n,d] for q,k,v
// ---------------------------------------------------------------------------
__global__ __launch_bounds__(256)
void cvt_kernel(const float* __restrict__ q, const float* __restrict__ k,
                const float* __restrict__ v)
{
    int c = blockIdx.x * 256 + threadIdx.x;   // 0 .. 524287 (8-half chunks)
    int which = blockIdx.y;
    const float* src = (which == 0) ? q : (which == 1) ? k : v;
    __half* dst = (which == 0) ? g_qh : (which == 1) ? g_kh : g_vh;

    int bh  = c >> 15;          // / (SEQ * 8)
    int rem = c & 32767;
    int n   = rem >> 3;
    int j   = rem & 7;
    int b = bh >> 3, h = bh & 7;

    const float4* in = (const float4*)(src + ((size_t)(b * SEQ + n)) * MODEL + h * HD + j * 8);
    float4 x = in[0], y = in[1];
    uint4 o;
    o.x = h2pack(x.x, x.y); o.y = h2pack(x.z, x.w);
    o.z = h2pack(y.x, y.y); o.w = h2pack(y.z, y.w);
    *(uint4*)(dst + (size_t)c * 8) = o;
}

// ---------------------------------------------------------------------------
// fp16 mma.sync flash attention. S via fp16-accumulate MMA (testing the
// double-rate hypothesis for the legacy HMMA path); O/L in fp32 accumulate.
// grid=(B*NH, SEQ/BM), block=128 (4 warps), 2 CTAs/SM.
// ---------------------------------------------------------------------------
__global__ __launch_bounds__(128, 2)
void attn_tc_kernel()
{
    extern __shared__ char smc[];
    const uint32_t sb = smem_u32(smc);

    const int tid  = threadIdx.x;
    const int lane = tid & 31;
    const int wid  = tid >> 5;
    const int g    = lane >> 2;
    const int t    = lane & 3;
    const int wq0  = wid * 32;

    const int bh = blockIdx.x;
    const int b  = bh >> 3;
    const int h  = bh & 7;
    const int q0 = blockIdx.y * BM;

    const __half* qh = g_qh + (size_t)bh * SEQ * HD;
    const __half* kh = g_kh + (size_t)bh * SEQ * HD;
    const __half* vh = g_vh + (size_t)bh * SEQ * HD;

    // ---- Stage this warp's 32 Q rows, then pull fragments into registers ----
#pragma unroll
    for (int it = 0; it < 8; it++) {
        int c = wq0 * 8 + it * 32 + lane;   // chunk: 8 x 16B per row
        int row = c >> 3, c16 = c & 7;
        *(uint4*)(smc + QS_B + row * RPITCH + c16 * 16) =
            *(const uint4*)(qh + (size_t)(q0 + row) * HD + c16 * 8);
    }
    __syncwarp();

    uint32_t qa[2][4][4];
#pragma unroll
    for (int m = 0; m < 2; m++)
#pragma unroll
        for (int s = 0; s < 4; s++) {
            uint32_t addr = sb + QS_B + (wq0 + 16 * m + (lane & 15)) * RPITCH
                          + ((lane >> 4) * 16) + s * 32;
            ldsm_x4(qa[m][s][0], qa[m][s][1], qa[m][s][2], qa[m][s][3], addr);
        }

    // Per-lane ldmatrix address bases (lane-dependent parts)
    const uint32_t koff = ((lane & 7) + ((lane >> 4) << 3)) * RPITCH
                        + ((lane >> 3) & 1) * 16;
    const uint32_t voff = ((lane & 7) + (((lane >> 3) & 1) << 3)) * RPITCH
                        + ((lane >> 4) & 1) * 16;

    // ---- Online-softmax state ----
    float mrow[2][2] = {{-1e30f, -1e30f}, {-1e30f, -1e30f}};
    float Lacc[2][4];            // l via ones-MMA: [m][0]=row g, [m][2]=row g+8
    float Oacc[2][8][4];
#pragma unroll
    for (int m = 0; m < 2; m++) {
#pragma unroll
        for (int i = 0; i < 4; i++) Lacc[m][i] = 0.f;
#pragma unroll
        for (int n = 0; n < 8; n++)
#pragma unroll
            for (int i = 0; i < 4; i++) Oacc[m][n][i] = 0.f;
    }

    // ---- Preload tile 0 (cp.async) ----
    {
#pragma unroll
        for (int r = 0; r < 4; r++) {
            int c = r * 128 + tid;
            int row = c >> 3, c16 = c & 7;
            cp_async16(sb + KS_B + row * RPITCH + c16 * 16,
                       kh + (size_t)row * HD + c16 * 8);
            cp_async16(sb + VS_B + row * RPITCH + c16 * 16,
                       vh + (size_t)row * HD + c16 * 8);
        }
        CP_COMMIT();
    }

    for (int kt = 0; kt < NTILES; kt++) {
        const int cur = kt & 1;
        __syncthreads();   // all warps done reading buf[cur^1] (iter kt-1)

        if (kt + 1 < NTILES) {
            const int j0 = (kt + 1) * BN;
            const uint32_t kb = sb + KS_B + (cur ^ 1) * 9216;
            const uint32_t vb = sb + VS_B + (cur ^ 1) * 9216;
#pragma unroll
            for (int r = 0; r < 4; r++) {
                int c = r * 128 + tid;
                int row = c >> 3, c16 = c & 7;
                cp_async16(kb + row * RPITCH + c16 * 16,
                           kh + (size_t)(j0 + row) * HD + c16 * 8);
                cp_async16(vb + row * RPITCH + c16 * 16,
                           vh + (size_t)(j0 + row) * HD + c16 * 8);
            }
            CP_COMMIT();
            CP_WAIT(1);    // tile kt complete (newest group may be in flight)
        } else {
            CP_WAIT(0);
        }
        __syncthreads();   // all warps' async portions of tile kt visible

        // ---- MMA1: S = Q . K^T  (fp16 accumulate; 2 packed regs per frag) ----
        uint32_t Sh[2][8][2];
#pragma unroll
        for (int m = 0; m < 2; m++)
#pragma unroll
            for (int n = 0; n < 8; n++) {
                Sh[m][n][0] = 0u; Sh[m][n][1] = 0u;
            }

        const uint32_t kbase = sb + KS_B + cur * 9216 + koff;
#pragma unroll
        for (int s = 0; s < 4; s++) {
#pragma unroll
            for (int np = 0; np < 4; np++) {
                uint32_t b0, b1, b2, b3;
                ldsm_x4(b0, b1, b2, b3, kbase + np * (16 * RPITCH) + s * 32);
                mma_f16h(Sh[0][2 * np],     qa[0][s], b0, b1);
                mma_f16h(Sh[0][2 * np + 1], qa[0][s], b2, b3);
                mma_f16h(Sh[1][2 * np],     qa[1][s], b0, b1);
                mma_f16h(Sh[1][2 * np + 1], qa[1][s], b2, b3);
            }
        }

        // ---- Unpack S to fp32, online softmax, exp in f16x2 ----
        uint32_t pa[2][4][4];
        float corr[2][2];
#pragma unroll
        for (int m = 0; m < 2; m++) {
            float S[8][4];
#pragma unroll
            for (int n = 0; n < 8; n++) {
                float2 p01 = __half22float2(*(__half2*)&Sh[m][n][0]);
                float2 p23 = __half22float2(*(__half2*)&Sh[m][n][1]);
                S[n][0] = p01.x; S[n][1] = p01.y;
                S[n][2] = p23.x; S[n][3] = p23.y;
            }
            float mtA = -1e30f, mtB = -1e30f;
#pragma unroll
            for (int n = 0; n < 8; n++) {
                mtA = fmaxf(mtA, fmaxf(S[n][0], S[n][1]));
                mtB = fmaxf(mtB, fmaxf(S[n][2], S[n][3]));
            }
            mtA = fmaxf(mtA, __shfl_xor_sync(0xFFFFFFFFu, mtA, 1));
            mtA = fmaxf(mtA, __shfl_xor_sync(0xFFFFFFFFu, mtA, 2));
            mtB = fmaxf(mtB, __shfl_xor_sync(0xFFFFFFFFu, mtB, 1));
            mtB = fmaxf(mtB, __shfl_xor_sync(0xFFFFFFFFu, mtB, 2));

            float mnA = fmaxf(mrow[m][0], mtA);
            float mnB = fmaxf(mrow[m][1], mtB);
            corr[m][0] = ex2((mrow[m][0] - mnA) * LS);
            corr[m][1] = ex2((mrow[m][1] - mnB) * LS);
            mrow[m][0] = mnA; mrow[m][1] = mnB;
            const float bA = mnA * LS, bB = mnB * LS;

#pragma unroll
            for (int s = 0; s < 4; s++) {
                pa[m][s][0] = ex2_h2(h2pack(fmaf(S[2*s][0],   LS, -bA),
                                            fmaf(S[2*s][1],   LS, -bA)));
                pa[m][s][1] = ex2_h2(h2pack(fmaf(S[2*s][2],   LS, -bB),
                                            fmaf(S[2*s][3],   LS, -bB)));
                pa[m][s][2] = ex2_h2(h2pack(fmaf(S[2*s+1][0], LS, -bA),
                                            fmaf(S[2*s+1][1], LS, -bA)));
                pa[m][s][3] = ex2_h2(h2pack(fmaf(S[2*s+1][2], LS, -bB),
                                            fmaf(S[2*s+1][3], LS, -bB)));
            }
        }

        // ---- Rescale O and L accumulators ----
#pragma unroll
        for (int m = 0; m < 2; m++) {
            Lacc[m][0] *= corr[m][0]; Lacc[m][1] *= corr[m][0];
            Lacc[m][2] *= corr[m][1]; Lacc[m][3] *= corr[m][1];
#pragma unroll
            for (int n = 0; n < 8; n++) {
                Oacc[m][n][0] *= corr[m][0]; Oacc[m][n][1] *= corr[m][0];
                Oacc[m][n][2] *= corr[m][1]; Oacc[m][n][3] *= corr[m][1];
            }
        }

        // ---- L += P . ones (row sums on the tensor pipe, quad-reduced) ----
#pragma unroll
        for (int s = 0; s < 4; s++) {
            mma_f16(Lacc[0], pa[0][s], ONES2, ONES2);
            mma_f16(Lacc[1], pa[1][s], ONES2, ONES2);
        }

        // ---- MMA2: O += P . V (fp32 accumulate) ----
        const uint32_t vbase = sb + VS_B + cur * 9216 + voff;
#pragma unroll
        for (int s = 0; s < 4; s++) {
#pragma unroll
            for (int nd = 0; nd < 4; nd++) {
                uint32_t b0, b1, b2, b3;
                ldsm_x4_t(b0, b1, b2, b3, vbase + s * (16 * RPITCH) + nd * 32);
                mma_f16(Oacc[0][2 * nd],     pa[0][s], b0, b1);
                mma_f16(Oacc[0][2 * nd + 1], pa[0][s], b2, b3);
                mma_f16(Oacc[1][2 * nd],     pa[1][s], b0, b1);
                mma_f16(Oacc[1][2 * nd + 1], pa[1][s], b2, b3);
            }
        }
    }

    // ---- Normalize (l already fully reduced), write to g_attn ----
#pragma unroll
    for (int m = 0; m < 2; m++) {
        float invA = 1.f / Lacc[m][0];
        float invB = 1.f / Lacc[m][2];
        int rA = q0 + wq0 + 16 * m + g;
        int rB = rA + 8;
        float* opA = g_attn + ((size_t)(b * SEQ + rA)) * MODEL + h * HD;
        float* opB = g_attn + ((size_t)(b * SEQ + rB)) * MODEL + h * HD;
#pragma unroll
        for (int n = 0; n < 8; n++) {
            *(float2*)(opA + n * 8 + 2 * t) =
                make_float2(Oacc[m][n][0] * invA, Oacc[m][n][1] * invA);
            *(float2*)(opB + n * 8 + 2 * t) =
                make_float2(Oacc[m][n][2] * invB, Oacc[m][n][3] * invB);
        }
    }
}

// ---------------------------------------------------------------------------
// Output projection: out[8192,64] = g_attn[8192,512] @ W[512,64] + b[64]
// 64 rows/block, 256 threads, 4x4 per thread, As padded (bank-spread).
// ---------------------------------------------------------------------------
#define GBM 64
#define GBK 64
#define APAD 68
__global__ __launch_bounds__(256)
void proj_kernel(const float* __restrict__ W,
                 const float* __restrict__ bias,
                 float* __restrict__ out)
{
    __shared__ float As[GBM][APAD];      // 17 KB
    __shared__ float Ws[GBK][64];        // 16 KB

    const int row0 = blockIdx.x * GBM;
    const int tid  = threadIdx.x;
    const int tr   = tid >> 4;
    const int tc   = tid & 15;

    float acc[4][4];
#pragma unroll
    for (int i = 0; i < 4; i++)
#pragma unroll
        for (int j = 0; j < 4; j++) acc[i][j] = 0.f;

    for (int k0 = 0; k0 < MODEL; k0 += GBK) {
#pragma unroll
        for (int it = 0; it < 4; it++) {
            int idx = it * 256 + tid;
            int r = idx >> 4, c4 = idx & 15;
            *(float4*)&As[r][c4 * 4] =
                *(const float4*)(g_attn + ((size_t)(row0 + r)) * MODEL + k0 + c4 * 4);
        }
#pragma unroll
        for (int it = 0; it < 4; it++) {
            int idx = it * 256 + tid;
            int r = idx >> 4, c4 = idx & 15;
            *(float4*)&Ws[r][c4 * 4] =
                *(const float4*)(W + ((size_t)(k0 + r)) * 64 + c4 * 4);
        }
        __syncthreads();

#pragma unroll
        for (int kk = 0; kk < GBK; kk++) {
            float4 w4 = *(const float4*)&Ws[kk][tc * 4];
#pragma unroll
            for (int i = 0; i < 4; i++) {
                float a = As[tr * 4 + i][kk];
                acc[i][0] += a * w4.x;
                acc[i][1] += a * w4.y;
                acc[i][2] += a * w4.z;
                acc[i][3] += a * w4.w;
            }
        }
        __syncthreads();
    }

#pragma unroll
    for (int i = 0; i < 4; i++) {
        int r = row0 + tr * 4 + i;
#pragma unroll
        for (int j = 0; j < 4; j++) {
            int c = tc * 4 + j;
            out[(size_t)r * 64 + c] = acc[i][j] + bias[c];
        }
    }
}

// ---------------------------------------------------------------------------
extern "C" void kernel_launch(void* const* d_in, const int* in_sizes, int n_in,
                              void* d_out, int out_size)
{
    const float* q    = (const float*)d_in[0];
    const float* k    = (const float*)d_in[1];
    const float* v    = (const float*)d_in[2];
    const float* Wout = (const float*)d_in[3];
    const float* bout = (const float*)d_in[4];
    float* out = (float*)d_out;

    static bool attr_set = false;
    if (!attr_set) {
        cudaFuncSetAttribute(attn_tc_kernel,
                             cudaFuncAttributeMaxDynamicSharedMemorySize, SMEM_BYTES);
        attr_set = true;
    }

    cvt_kernel<<<dim3(2048, 3), 256>>>(q, k, v);

    dim3 agrid(BATCH * NH, SEQ / BM);
    attn_tc_kernel<<<agrid, BM, SMEM_BYTES>>>();

    dim3 pgrid((BATCH * SEQ) / GBM);
    proj_kernel<<<pgrid, 256>>>(Wout, bout, out);
}

// round 10
// speedup vs baseline: 1.4643x; 1.4643x over previous
#include <cuda_runtime.h>
#include <cuda_fp16.h>
#include <cstdint>

// (B, N, H, D) = (2, 4096, 8, 64)
#define BATCH 2
#define SEQ   4096
#define NH    8
#define HD    64
#define MODEL 512
#define BM    128            // query rows per CTA (8 warps x 16)
#define BN    64             // keys per tile
#define NTILES (SEQ / BN)    // 64
#define LS 0.180336879f      // 0.125 * log2(e): exp(s/8) = exp2(s*LS)
#define ONES2 0x3C003C00u    // half2(1.0, 1.0)

// Device scratch (no cudaMalloc allowed)
__device__ __align__(16) float  g_attn[(size_t)BATCH * SEQ * MODEL];
__device__ __align__(16) __half g_qh[(size_t)BATCH * NH * SEQ * HD];
__device__ __align__(16) __half g_kh[(size_t)BATCH * NH * SEQ * HD];
__device__ __align__(16) __half g_vh[(size_t)BATCH * NH * SEQ * HD];

// SMEM layout (bytes). Row pitch = 64 halfs + 8 pad = 144 B (conflict-free).
#define RPITCH 144
#define QS_B 0                       // 128 * 144 = 18432
#define KS_B 18432                   // 2 x (64*144 = 9216)
#define VS_B (KS_B + 2 * 9216)       // 36864
#define SMEM_BYTES (VS_B + 2 * 9216) // 55296

__device__ __forceinline__ uint32_t smem_u32(const void* p) {
    uint32_t a;
    asm("{ .reg .u64 t; cvta.to.shared.u64 t, %1; cvt.u32.u64 %0, t; }"
        : "=r"(a) : "l"(p));
    return a;
}
__device__ __forceinline__ float ex2(float x) {
    float r; asm("ex2.approx.ftz.f32 %0, %1;" : "=f"(r) : "f"(x)); return r;
}
__device__ __forceinline__ uint32_t ex2_h2(uint32_t x) {
    uint32_t r; asm("ex2.approx.f16x2 %0, %1;" : "=r"(r) : "r"(x)); return r;
}
__device__ __forceinline__ void cp_async16(uint32_t dst, const void* src) {
    asm volatile("cp.async.cg.shared.global [%0], [%1], 16;"
                 :: "r"(dst), "l"(src) : "memory");
}
#define CP_COMMIT() asm volatile("cp.async.commit_group;" ::: "memory")
#define CP_WAIT(n)  asm volatile("cp.async.wait_group %0;" :: "n"(n) : "memory")

__device__ __forceinline__ void ldsm_x4(uint32_t& r0, uint32_t& r1,
                                        uint32_t& r2, uint32_t& r3, uint32_t a) {
    asm volatile("ldmatrix.sync.aligned.m8n8.x4.shared.b16 {%0,%1,%2,%3}, [%4];"
                 : "=r"(r0), "=r"(r1), "=r"(r2), "=r"(r3) : "r"(a));
}
__device__ __forceinline__ void ldsm_x4_t(uint32_t& r0, uint32_t& r1,
                                          uint32_t& r2, uint32_t& r3, uint32_t a) {
    asm volatile("ldmatrix.sync.aligned.m8n8.x4.trans.shared.b16 {%0,%1,%2,%3}, [%4];"
                 : "=r"(r0), "=r"(r1), "=r"(r2), "=r"(r3) : "r"(a));
}
__device__ __forceinline__ void mma_f16(float c[4], const uint32_t a[4],
                                        uint32_t b0, uint32_t b1) {
    asm volatile(
        "mma.sync.aligned.m16n8k16.row.col.f32.f16.f16.f32 "
        "{%0,%1,%2,%3}, {%4,%5,%6,%7}, {%8,%9}, {%0,%1,%2,%3};"
        : "+f"(c[0]), "+f"(c[1]), "+f"(c[2]), "+f"(c[3])
        : "r"(a[0]), "r"(a[1]), "r"(a[2]), "r"(a[3]), "r"(b0), "r"(b1));
}
__device__ __forceinline__ uint32_t h2pack(float a, float b) {
    __half2 h = __floats2half2_rn(a, b);
    return *reinterpret_cast<uint32_t*>(&h);
}

// ---------------------------------------------------------------------------
// Prolog: fp32 [b,n,h*d] -> fp16 [b,h,n,d] for q,k,v
// ---------------------------------------------------------------------------
__global__ __launch_bounds__(256)
void cvt_kernel(const float* __restrict__ q, const float* __restrict__ k,
                const float* __restrict__ v)
{
    int c = blockIdx.x * 256 + threadIdx.x;   // 0 .. 524287 (8-half chunks)
    int which = blockIdx.y;
    const float* src = (which == 0) ? q : (which == 1) ? k : v;
    __half* dst = (which == 0) ? g_qh : (which == 1) ? g_kh : g_vh;

    int bh  = c >> 15;          // / (SEQ * 8)
    int rem = c & 32767;
    int n   = rem >> 3;
    int j   = rem & 7;
    int b = bh >> 3, h = bh & 7;

    const float4* in = (const float4*)(src + ((size_t)(b * SEQ + n)) * MODEL + h * HD + j * 8);
    float4 x = in[0], y = in[1];
    uint4 o;
    o.x = h2pack(x.x, x.y); o.y = h2pack(x.z, x.w);
    o.z = h2pack(y.x, y.y); o.w = h2pack(y.z, y.w);
    *(uint4*)(dst + (size_t)c * 8) = o;
}

// ---------------------------------------------------------------------------
// fp16 mma.sync flash attention, 8 warps x 16 q-rows (4 warps/SMSP for
// latency overlap). fp32 accumulate everywhere; h2 exp; l via ones-MMA.
// grid=(B*NH, SEQ/BM), block=256, 2 CTAs/SM.
// ---------------------------------------------------------------------------
__global__ __launch_bounds__(256, 2)
void attn_tc_kernel()
{
    extern __shared__ char smc[];
    const uint32_t sb = smem_u32(smc);

    const int tid  = threadIdx.x;
    const int lane = tid & 31;
    const int wid  = tid >> 5;      // 0..7
    const int g    = lane >> 2;
    const int t    = lane & 3;
    const int wq0  = wid * 16;      // warp's 16 query rows

    const int bh = blockIdx.x;
    const int b  = bh >> 3;
    const int h  = bh & 7;
    const int q0 = blockIdx.y * BM;

    const __half* qh = g_qh + (size_t)bh * SEQ * HD;
    const __half* kh = g_kh + (size_t)bh * SEQ * HD;
    const __half* vh = g_vh + (size_t)bh * SEQ * HD;

    // ---- Stage this warp's 16 Q rows, then pull fragments into registers ----
#pragma unroll
    for (int it = 0; it < 4; it++) {
        int c = wq0 * 8 + it * 32 + lane;   // 16 rows x 8 chunks = 128 chunks
        int row = c >> 3, c16 = c & 7;
        *(uint4*)(smc + QS_B + row * RPITCH + c16 * 16) =
            *(const uint4*)(qh + (size_t)(q0 + row) * HD + c16 * 8);
    }
    __syncwarp();

    uint32_t qa[4][4];
#pragma unroll
    for (int s = 0; s < 4; s++) {
        uint32_t addr = sb + QS_B + (wq0 + (lane & 15)) * RPITCH
                      + ((lane >> 4) * 16) + s * 32;
        ldsm_x4(qa[s][0], qa[s][1], qa[s][2], qa[s][3], addr);
    }

    // Per-lane ldmatrix address bases (lane-dependent parts)
    const uint32_t koff = ((lane & 7) + ((lane >> 4) << 3)) * RPITCH
                        + ((lane >> 3) & 1) * 16;
    const uint32_t voff = ((lane & 7) + (((lane >> 3) & 1) << 3)) * RPITCH
                        + ((lane >> 4) & 1) * 16;

    // ---- Online-softmax state (one 16-row m-tile per warp) ----
    float mA = -1e30f, mB = -1e30f;
    float Lacc[4];                 // l via ones-MMA: [0]=row g, [2]=row g+8
    float Oacc[8][4];
#pragma unroll
    for (int i = 0; i < 4; i++) Lacc[i] = 0.f;
#pragma unroll
    for (int n = 0; n < 8; n++)
#pragma unroll
        for (int i = 0; i < 4; i++) Oacc[n][i] = 0.f;

    // ---- Preload tile 0 (cp.async): 1024 chunks over 256 threads ----
    {
#pragma unroll
        for (int r = 0; r < 2; r++) {
            int c = r * 256 + tid;
            int row = c >> 3, c16 = c & 7;
            cp_async16(sb + KS_B + row * RPITCH + c16 * 16,
                       kh + (size_t)row * HD + c16 * 8);
            cp_async16(sb + VS_B + row * RPITCH + c16 * 16,
                       vh + (size_t)row * HD + c16 * 8);
        }
        CP_COMMIT();
    }

    for (int kt = 0; kt < NTILES; kt++) {
        const int cur = kt & 1;
        __syncthreads();   // all warps done reading buf[cur^1] (iter kt-1)

        if (kt + 1 < NTILES) {
            const int j0 = (kt + 1) * BN;
            const uint32_t kb = sb + KS_B + (cur ^ 1) * 9216;
            const uint32_t vb = sb + VS_B + (cur ^ 1) * 9216;
#pragma unroll
            for (int r = 0; r < 2; r++) {
                int c = r * 256 + tid;
                int row = c >> 3, c16 = c & 7;
                cp_async16(kb + row * RPITCH + c16 * 16,
                           kh + (size_t)(j0 + row) * HD + c16 * 8);
                cp_async16(vb + row * RPITCH + c16 * 16,
                           vh + (size_t)(j0 + row) * HD + c16 * 8);
            }
            CP_COMMIT();
            CP_WAIT(1);    // tile kt complete (newest group may be in flight)
        } else {
            CP_WAIT(0);
        }
        __syncthreads();   // all warps' async portions of tile kt visible

        // ---- MMA1: S[16,64] = Q . K^T ----
        float S[8][4];
#pragma unroll
        for (int n = 0; n < 8; n++)
#pragma unroll
            for (int i = 0; i < 4; i++) S[n][i] = 0.f;

        const uint32_t kbase = sb + KS_B + cur * 9216 + koff;
#pragma unroll
        for (int s = 0; s < 4; s++) {
#pragma unroll
            for (int np = 0; np < 4; np++) {
                uint32_t b0, b1, b2, b3;
                ldsm_x4(b0, b1, b2, b3, kbase + np * (16 * RPITCH) + s * 32);
                mma_f16(S[2 * np],     qa[s], b0, b1);
                mma_f16(S[2 * np + 1], qa[s], b2, b3);
            }
        }

        // ---- Online softmax: args in fp32, exp in f16x2 (packed = P frag) ----
        float mtA = -1e30f, mtB = -1e30f;
#pragma unroll
        for (int n = 0; n < 8; n++) {
            mtA = fmaxf(mtA, fmaxf(S[n][0], S[n][1]));
            mtB = fmaxf(mtB, fmaxf(S[n][2], S[n][3]));
        }
        mtA = fmaxf(mtA, __shfl_xor_sync(0xFFFFFFFFu, mtA, 1));
        mtA = fmaxf(mtA, __shfl_xor_sync(0xFFFFFFFFu, mtA, 2));
        mtB = fmaxf(mtB, __shfl_xor_sync(0xFFFFFFFFu, mtB, 1));
        mtB = fmaxf(mtB, __shfl_xor_sync(0xFFFFFFFFu, mtB, 2));

        float mnA = fmaxf(mA, mtA);
        float mnB = fmaxf(mB, mtB);
        float corrA = ex2((mA - mnA) * LS);
        float corrB = ex2((mB - mnB) * LS);
        mA = mnA; mB = mnB;
        const float bA = mnA * LS, bB = mnB * LS;

        uint32_t pa[4][4];
#pragma unroll
        for (int s = 0; s < 4; s++) {
            pa[s][0] = ex2_h2(h2pack(fmaf(S[2*s][0],   LS, -bA),
                                     fmaf(S[2*s][1],   LS, -bA)));
            pa[s][1] = ex2_h2(h2pack(fmaf(S[2*s][2],   LS, -bB),
                                     fmaf(S[2*s][3],   LS, -bB)));
            pa[s][2] = ex2_h2(h2pack(fmaf(S[2*s+1][0], LS, -bA),
                                     fmaf(S[2*s+1][1], LS, -bA)));
            pa[s][3] = ex2_h2(h2pack(fmaf(S[2*s+1][2], LS, -bB),
                                     fmaf(S[2*s+1][3], LS, -bB)));
        }

        // ---- Rescale O and L accumulators ----
        Lacc[0] *= corrA; Lacc[1] *= corrA;
        Lacc[2] *= corrB; Lacc[3] *= corrB;
#pragma unroll
        for (int n = 0; n < 8; n++) {
            Oacc[n][0] *= corrA; Oacc[n][1] *= corrA;
            Oacc[n][2] *= corrB; Oacc[n][3] *= corrB;
        }

        // ---- L += P . ones (row sums on the tensor pipe, quad-reduced) ----
#pragma unroll
        for (int s = 0; s < 4; s++)
            mma_f16(Lacc, pa[s], ONES2, ONES2);

        // ---- MMA2: O += P . V ----
        const uint32_t vbase = sb + VS_B + cur * 9216 + voff;
#pragma unroll
        for (int s = 0; s < 4; s++) {
#pragma unroll
            for (int nd = 0; nd < 4; nd++) {
                uint32_t b0, b1, b2, b3;
                ldsm_x4_t(b0, b1, b2, b3, vbase + s * (16 * RPITCH) + nd * 32);
                mma_f16(Oacc[2 * nd],     pa[s], b0, b1);
                mma_f16(Oacc[2 * nd + 1], pa[s], b2, b3);
            }
        }
    }

    // ---- Normalize (l already fully reduced), write to g_attn ----
    {
        float invA = 1.f / Lacc[0];
        float invB = 1.f / Lacc[2];
        int rA = q0 + wq0 + g;
        int rB = rA + 8;
        float* opA = g_attn + ((size_t)(b * SEQ + rA)) * MODEL + h * HD;
        float* opB = g_attn + ((size_t)(b * SEQ + rB)) * MODEL + h * HD;
#pragma unroll
        for (int n = 0; n < 8; n++) {
            *(float2*)(opA + n * 8 + 2 * t) =
                make_float2(Oacc[n][0] * invA, Oacc[n][1] * invA);
            *(float2*)(opB + n * 8 + 2 * t) =
                make_float2(Oacc[n][2] * invB, Oacc[n][3] * invB);
        }
    }
}

// ---------------------------------------------------------------------------
// Output projection: out[8192,64] = g_attn[8192,512] @ W[512,64] + b[64]
// 64 rows/block, 256 threads, 4x4 per thread, As padded (bank-spread).
// ---------------------------------------------------------------------------
#define GBM 64
#define GBK 64
#define APAD 68
__global__ __launch_bounds__(256)
void proj_kernel(const float* __restrict__ W,
                 const float* __restrict__ bias,
                 float* __restrict__ out)
{
    __shared__ float As[GBM][APAD];      // 17 KB
    __shared__ float Ws[GBK][64];        // 16 KB

    const int row0 = blockIdx.x * GBM;
    const int tid  = threadIdx.x;
    const int tr   = tid >> 4;
    const int tc   = tid & 15;

    float acc[4][4];
#pragma unroll
    for (int i = 0; i < 4; i++)
#pragma unroll
        for (int j = 0; j < 4; j++) acc[i][j] = 0.f;

    for (int k0 = 0; k0 < MODEL; k0 += GBK) {
#pragma unroll
        for (int it = 0; it < 4; it++) {
            int idx = it * 256 + tid;
            int r = idx >> 4, c4 = idx & 15;
            *(float4*)&As[r][c4 * 4] =
                *(const float4*)(g_attn + ((size_t)(row0 + r)) * MODEL + k0 + c4 * 4);
        }
#pragma unroll
        for (int it = 0; it < 4; it++) {
            int idx = it * 256 + tid;
            int r = idx >> 4, c4 = idx & 15;
            *(float4*)&Ws[r][c4 * 4] =
                *(const float4*)(W + ((size_t)(k0 + r)) * 64 + c4 * 4);
        }
        __syncthreads();

#pragma unroll
        for (int kk = 0; kk < GBK; kk++) {
            float4 w4 = *(const float4*)&Ws[kk][tc * 4];
#pragma unroll
            for (int i = 0; i < 4; i++) {
                float a = As[tr * 4 + i][kk];
                acc[i][0] += a * w4.x;
                acc[i][1] += a * w4.y;
                acc[i][2] += a * w4.z;
                acc[i][3] += a * w4.w;
            }
        }
        __syncthreads();
    }

#pragma unroll
    for (int i = 0; i < 4; i++) {
        int r = row0 + tr * 4 + i;
#pragma unroll
        for (int j = 0; j < 4; j++) {
            int c = tc * 4 + j;
            out[(size_t)r * 64 + c] = acc[i][j] + bias[c];
        }
    }
}

// ---------------------------------------------------------------------------
extern "C" void kernel_launch(void* const* d_in, const int* in_sizes, int n_in,
                              void* d_out, int out_size)
{
    const float* q    = (const float*)d_in[0];
    const float* k    = (const float*)d_in[1];
    const float* v    = (const float*)d_in[2];
    const float* Wout = (const float*)d_in[3];
    const float* bout = (const float*)d_in[4];
    float* out = (float*)d_out;

    static bool attr_set = false;
    if (!attr_set) {
        cudaFuncSetAttribute(attn_tc_kernel,
                             cudaFuncAttributeMaxDynamicSharedMemorySize, SMEM_BYTES);
        attr_set = true;
    }

    cvt_kernel<<<dim3(2048, 3), 256>>>(q, k, v);

    dim3 agrid(BATCH * NH, SEQ / BM);
    attn_tc_kernel<<<agrid, 256, SMEM_BYTES>>>();

    dim3 pgrid((BATCH * SEQ) / GBM);
    proj_kernel<<<pgrid, 256>>>(Wout, bout, out);
}

// round 11
// speedup vs baseline: 1.5141x; 1.0340x over previous
#include <cuda_runtime.h>
#include <cuda_fp16.h>
#include <cstdint>

// (B, N, H, D) = (2, 4096, 8, 64)
#define BATCH 2
#define SEQ   4096
#define NH    8
#define HD    64
#define MODEL 512
#define BM    128            // query rows per CTA (4 warps x 32)
#define BN    64             // keys per tile
#define NTILES (SEQ / BN)    // 64
#define LS 0.180336879f      // 0.125 * log2(e): exp(s/8) = exp2(s*LS)
#define ONES2 0x3C003C00u    // half2(1.0, 1.0)

// Device scratch (no cudaMalloc allowed)
__device__ __align__(16) float  g_attn[(size_t)BATCH * SEQ * MODEL];
__device__ __align__(16) __half g_qh[(size_t)BATCH * NH * SEQ * HD];
__device__ __align__(16) __half g_kh[(size_t)BATCH * NH * SEQ * HD];
__device__ __align__(16) __half g_vh[(size_t)BATCH * NH * SEQ * HD];

// SMEM layout (bytes). Row pitch = 64 halfs + 8 pad = 144 B (conflict-free).
// Triple-buffered K/V.
#define RPITCH 144
#define TBUF   9216                  // 64 * 144
#define QS_B 0                       // 128 * 144 = 18432
#define KS_B 18432                   // 3 x 9216
#define VS_B (KS_B + 3 * TBUF)       // 46080
#define SMEM_BYTES (VS_B + 3 * TBUF) // 73728 (x2 CTAs = 144 KB/SM)

__device__ __forceinline__ uint32_t smem_u32(const void* p) {
    uint32_t a;
    asm("{ .reg .u64 t; cvta.to.shared.u64 t, %1; cvt.u32.u64 %0, t; }"
        : "=r"(a) : "l"(p));
    return a;
}
__device__ __forceinline__ float ex2(float x) {
    float r; asm("ex2.approx.ftz.f32 %0, %1;" : "=f"(r) : "f"(x)); return r;
}
__device__ __forceinline__ uint32_t ex2_h2(uint32_t x) {
    uint32_t r; asm("ex2.approx.f16x2 %0, %1;" : "=r"(r) : "r"(x)); return r;
}
__device__ __forceinline__ void cp_async16(uint32_t dst, const void* src) {
    asm volatile("cp.async.cg.shared.global [%0], [%1], 16;"
                 :: "r"(dst), "l"(src) : "memory");
}
#define CP_COMMIT() asm volatile("cp.async.commit_group;" ::: "memory")
#define CP_WAIT(n)  asm volatile("cp.async.wait_group %0;" :: "n"(n) : "memory")

__device__ __forceinline__ void ldsm_x4(uint32_t& r0, uint32_t& r1,
                                        uint32_t& r2, uint32_t& r3, uint32_t a) {
    asm volatile("ldmatrix.sync.aligned.m8n8.x4.shared.b16 {%0,%1,%2,%3}, [%4];"
                 : "=r"(r0), "=r"(r1), "=r"(r2), "=r"(r3) : "r"(a));
}
__device__ __forceinline__ void ldsm_x4_t(uint32_t& r0, uint32_t& r1,
                                          uint32_t& r2, uint32_t& r3, uint32_t a) {
    asm volatile("ldmatrix.sync.aligned.m8n8.x4.trans.shared.b16 {%0,%1,%2,%3}, [%4];"
                 : "=r"(r0), "=r"(r1), "=r"(r2), "=r"(r3) : "r"(a));
}
__device__ __forceinline__ void mma_f16(float c[4], const uint32_t a[4],
                                        uint32_t b0, uint32_t b1) {
    asm volatile(
        "mma.sync.aligned.m16n8k16.row.col.f32.f16.f16.f32 "
        "{%0,%1,%2,%3}, {%4,%5,%6,%7}, {%8,%9}, {%0,%1,%2,%3};"
        : "+f"(c[0]), "+f"(c[1]), "+f"(c[2]), "+f"(c[3])
        : "r"(a[0]), "r"(a[1]), "r"(a[2]), "r"(a[3]), "r"(b0), "r"(b1));
}
__device__ __forceinline__ uint32_t h2pack(float a, float b) {
    __half2 h = __floats2half2_rn(a, b);
    return *reinterpret_cast<uint32_t*>(&h);
}

// ---------------------------------------------------------------------------
// Prolog: fp32 [b,n,h*d] -> fp16 [b,h,n,d] for q,k,v
// ---------------------------------------------------------------------------
__global__ __launch_bounds__(256)
void cvt_kernel(const float* __restrict__ q, const float* __restrict__ k,
                const float* __restrict__ v)
{
    int c = blockIdx.x * 256 + threadIdx.x;   // 0 .. 524287 (8-half chunks)
    int which = blockIdx.y;
    const float* src = (which == 0) ? q : (which == 1) ? k : v;
    __half* dst = (which == 0) ? g_qh : (which == 1) ? g_kh : g_vh;

    int bh  = c >> 15;          // / (SEQ * 8)
    int rem = c & 32767;
    int n   = rem >> 3;
    int j   = rem & 7;
    int b = bh >> 3, h = bh & 7;

    const float4* in = (const float4*)(src + ((size_t)(b * SEQ + n)) * MODEL + h * HD + j * 8);
    float4 x = in[0], y = in[1];
    uint4 o;
    o.x = h2pack(x.x, x.y); o.y = h2pack(x.z, x.w);
    o.z = h2pack(y.x, y.y); o.w = h2pack(y.z, y.w);
    *(uint4*)(dst + (size_t)c * 8) = o;
}

// ---------------------------------------------------------------------------
// fp16 mma.sync flash attention. Triple-buffered K/V (1 barrier/tile),
// per-m-tile softmax->MMA2 interleave to hide the softmax latency chain
// behind the tensor pipe. fp32 accumulate; h2 exp; l via ones-MMA.
// grid=(B*NH, SEQ/BM), block=128 (4 warps), 2 CTAs/SM.
// ---------------------------------------------------------------------------
__global__ __launch_bounds__(128, 2)
void attn_tc_kernel()
{
    extern __shared__ char smc[];
    const uint32_t sb = smem_u32(smc);

    const int tid  = threadIdx.x;
    const int lane = tid & 31;
    const int wid  = tid >> 5;
    const int g    = lane >> 2;
    const int t    = lane & 3;
    const int wq0  = wid * 32;

    const int bh = blockIdx.x;
    const int b  = bh >> 3;
    const int h  = bh & 7;
    const int q0 = blockIdx.y * BM;

    const __half* qh = g_qh + (size_t)bh * SEQ * HD;
    const __half* kh = g_kh + (size_t)bh * SEQ * HD;
    const __half* vh = g_vh + (size_t)bh * SEQ * HD;

    // ---- Stage this warp's 32 Q rows, then pull fragments into registers ----
#pragma unroll
    for (int it = 0; it < 8; it++) {
        int c = wq0 * 8 + it * 32 + lane;   // chunk: 8 x 16B per row
        int row = c >> 3, c16 = c & 7;
        *(uint4*)(smc + QS_B + row * RPITCH + c16 * 16) =
            *(const uint4*)(qh + (size_t)(q0 + row) * HD + c16 * 8);
    }
    __syncwarp();

    uint32_t qa[2][4][4];
#pragma unroll
    for (int m = 0; m < 2; m++)
#pragma unroll
        for (int s = 0; s < 4; s++) {
            uint32_t addr = sb + QS_B + (wq0 + 16 * m + (lane & 15)) * RPITCH
                          + ((lane >> 4) * 16) + s * 32;
            ldsm_x4(qa[m][s][0], qa[m][s][1], qa[m][s][2], qa[m][s][3], addr);
        }

    // Per-lane ldmatrix address bases (lane-dependent parts)
    const uint32_t koff = ((lane & 7) + ((lane >> 4) << 3)) * RPITCH
                        + ((lane >> 3) & 1) * 16;
    const uint32_t voff = ((lane & 7) + (((lane >> 3) & 1) << 3)) * RPITCH
                        + ((lane >> 4) & 1) * 16;

    // ---- Online-softmax state ----
    float mrow[2][2] = {{-1e30f, -1e30f}, {-1e30f, -1e30f}};
    float Lacc[2][4];            // l via ones-MMA: [m][0]=row g, [m][2]=row g+8
    float Oacc[2][8][4];
#pragma unroll
    for (int m = 0; m < 2; m++) {
#pragma unroll
        for (int i = 0; i < 4; i++) Lacc[m][i] = 0.f;
#pragma unroll
        for (int n = 0; n < 8; n++)
#pragma unroll
            for (int i = 0; i < 4; i++) Oacc[m][n][i] = 0.f;
    }

    // ---- Preload tiles 0 and 1 (two cp.async groups) ----
#pragma unroll
    for (int pt = 0; pt < 2; pt++) {
        const uint32_t kb = sb + KS_B + pt * TBUF;
        const uint32_t vb = sb + VS_B + pt * TBUF;
        const int j0 = pt * BN;
#pragma unroll
        for (int r = 0; r < 4; r++) {
            int c = r * 128 + tid;
            int row = c >> 3, c16 = c & 7;
            cp_async16(kb + row * RPITCH + c16 * 16,
                       kh + (size_t)(j0 + row) * HD + c16 * 8);
            cp_async16(vb + row * RPITCH + c16 * 16,
                       vh + (size_t)(j0 + row) * HD + c16 * 8);
        }
        CP_COMMIT();
    }

    for (int kt = 0; kt < NTILES; kt++) {
        const int cur = kt % 3;

        // Wait for tile kt (outstanding after wait: tile kt+1's group)
        if (kt + 1 < NTILES) { CP_WAIT(1); } else { CP_WAIT(0); }
        __syncthreads();   // tile kt visible to all; all warps done with kt-1

        // Prefetch tile kt+2 into buffer (kt+2)%3 == (kt-1)%3 (freed at kt-1,
        // protected by the barrier above).
        if (kt + 2 < NTILES) {
            const int j0 = (kt + 2) * BN;
            const int nb = (kt + 2) % 3;
            const uint32_t kb = sb + KS_B + nb * TBUF;
            const uint32_t vb = sb + VS_B + nb * TBUF;
#pragma unroll
            for (int r = 0; r < 4; r++) {
                int c = r * 128 + tid;
                int row = c >> 3, c16 = c & 7;
                cp_async16(kb + row * RPITCH + c16 * 16,
                           kh + (size_t)(j0 + row) * HD + c16 * 8);
                cp_async16(vb + row * RPITCH + c16 * 16,
                           vh + (size_t)(j0 + row) * HD + c16 * 8);
            }
            CP_COMMIT();
        }

        // ---- MMA1: S = Q . K^T (both m-tiles; shared K frags) ----
        float S[2][8][4];
#pragma unroll
        for (int m = 0; m < 2; m++)
#pragma unroll
            for (int n = 0; n < 8; n++)
#pragma unroll
                for (int i = 0; i < 4; i++) S[m][n][i] = 0.f;

        const uint32_t kbase = sb + KS_B + cur * TBUF + koff;
#pragma unroll
        for (int s = 0; s < 4; s++) {
#pragma unroll
            for (int np = 0; np < 4; np++) {
                uint32_t b0, b1, b2, b3;
                ldsm_x4(b0, b1, b2, b3, kbase + np * (16 * RPITCH) + s * 32);
                mma_f16(S[0][2 * np],     qa[0][s], b0, b1);
                mma_f16(S[0][2 * np + 1], qa[0][s], b2, b3);
                mma_f16(S[1][2 * np],     qa[1][s], b0, b1);
                mma_f16(S[1][2 * np + 1], qa[1][s], b2, b3);
            }
        }

        // ---- Per-m pipeline: softmax(m) -> MMA2(m). softmax(m1) issues
        //      while the tensor pipe drains m0's MMA2s. ----
        const uint32_t vbase = sb + VS_B + cur * TBUF + voff;
#pragma unroll
        for (int m = 0; m < 2; m++) {
            float mtA = -1e30f, mtB = -1e30f;
#pragma unroll
            for (int n = 0; n < 8; n++) {
                mtA = fmaxf(mtA, fmaxf(S[m][n][0], S[m][n][1]));
                mtB = fmaxf(mtB, fmaxf(S[m][n][2], S[m][n][3]));
            }
            mtA = fmaxf(mtA, __shfl_xor_sync(0xFFFFFFFFu, mtA, 1));
            mtA = fmaxf(mtA, __shfl_xor_sync(0xFFFFFFFFu, mtA, 2));
            mtB = fmaxf(mtB, __shfl_xor_sync(0xFFFFFFFFu, mtB, 1));
            mtB = fmaxf(mtB, __shfl_xor_sync(0xFFFFFFFFu, mtB, 2));

            float mnA = fmaxf(mrow[m][0], mtA);
            float mnB = fmaxf(mrow[m][1], mtB);
            float corrA = ex2((mrow[m][0] - mnA) * LS);
            float corrB = ex2((mrow[m][1] - mnB) * LS);
            mrow[m][0] = mnA; mrow[m][1] = mnB;
            const float bA = mnA * LS, bB = mnB * LS;

            uint32_t pa[4][4];
#pragma unroll
            for (int s = 0; s < 4; s++) {
                pa[s][0] = ex2_h2(h2pack(fmaf(S[m][2*s][0],   LS, -bA),
                                         fmaf(S[m][2*s][1],   LS, -bA)));
                pa[s][1] = ex2_h2(h2pack(fmaf(S[m][2*s][2],   LS, -bB),
                                         fmaf(S[m][2*s][3],   LS, -bB)));
                pa[s][2] = ex2_h2(h2pack(fmaf(S[m][2*s+1][0], LS, -bA),
                                         fmaf(S[m][2*s+1][1], LS, -bA)));
                pa[s][3] = ex2_h2(h2pack(fmaf(S[m][2*s+1][2], LS, -bB),
                                         fmaf(S[m][2*s+1][3], LS, -bB)));
            }

            // Rescale O/L accumulators of this m-tile
            Lacc[m][0] *= corrA; Lacc[m][1] *= corrA;
            Lacc[m][2] *= corrB; Lacc[m][3] *= corrB;
#pragma unroll
            for (int n = 0; n < 8; n++) {
                Oacc[m][n][0] *= corrA; Oacc[m][n][1] *= corrA;
                Oacc[m][n][2] *= corrB; Oacc[m][n][3] *= corrB;
            }

            // L += P . ones
#pragma unroll
            for (int s = 0; s < 4; s++)
                mma_f16(Lacc[m], pa[s], ONES2, ONES2);

            // MMA2(m): O += P . V
#pragma unroll
            for (int s = 0; s < 4; s++) {
#pragma unroll
                for (int nd = 0; nd < 4; nd++) {
                    uint32_t b0, b1, b2, b3;
                    ldsm_x4_t(b0, b1, b2, b3,
                              vbase + s * (16 * RPITCH) + nd * 32);
                    mma_f16(Oacc[m][2 * nd],     pa[s], b0, b1);
                    mma_f16(Oacc[m][2 * nd + 1], pa[s], b2, b3);
                }
            }
        }
    }

    // ---- Normalize (l already fully reduced), write to g_attn ----
#pragma unroll
    for (int m = 0; m < 2; m++) {
        float invA = 1.f / Lacc[m][0];
        float invB = 1.f / Lacc[m][2];
        int rA = q0 + wq0 + 16 * m + g;
        int rB = rA + 8;
        float* opA = g_attn + ((size_t)(b * SEQ + rA)) * MODEL + h * HD;
        float* opB = g_attn + ((size_t)(b * SEQ + rB)) * MODEL + h * HD;
#pragma unroll
        for (int n = 0; n < 8; n++) {
            *(float2*)(opA + n * 8 + 2 * t) =
                make_float2(Oacc[m][n][0] * invA, Oacc[m][n][1] * invA);
            *(float2*)(opB + n * 8 + 2 * t) =
                make_float2(Oacc[m][n][2] * invB, Oacc[m][n][3] * invB);
        }
    }
}

// ---------------------------------------------------------------------------
// Output projection: out[8192,64] = g_attn[8192,512] @ W[512,64] + b[64]
// GBM=32 rows/block, 256 threads, 2x4 per thread -> 256 CTAs (was 128:
// a single partial wave on 148 SMs).
// ---------------------------------------------------------------------------
#define GBM 32
#define GBK 64
#define APAD 68
__global__ __launch_bounds__(256)
void proj_kernel(const float* __restrict__ W,
                 const float* __restrict__ bias,
                 float* __restrict__ out)
{
    __shared__ float As[GBM][APAD];      // 8.5 KB
    __shared__ float Ws[GBK][64];        // 16 KB

    const int row0 = blockIdx.x * GBM;
    const int tid  = threadIdx.x;
    const int tr   = tid >> 4;           // 0..15 -> rows tr*2, tr*2+1
    const int tc   = tid & 15;           // cols tc*4..tc*4+3

    float acc[2][4];
#pragma unroll
    for (int i = 0; i < 2; i++)
#pragma unroll
        for (int j = 0; j < 4; j++) acc[i][j] = 0.f;

    for (int k0 = 0; k0 < MODEL; k0 += GBK) {
        // As: 32x64 floats = 512 float4 over 256 threads -> 2 each
#pragma unroll
        for (int it = 0; it < 2; it++) {
            int idx = it * 256 + tid;
            int r = idx >> 4, c4 = idx & 15;
            *(float4*)&As[r][c4 * 4] =
                *(const float4*)(g_attn + ((size_t)(row0 + r)) * MODEL + k0 + c4 * 4);
        }
        // Ws: 64x64 floats = 1024 float4 -> 4 each
#pragma unroll
        for (int it = 0; it < 4; it++) {
            int idx = it * 256 + tid;
            int r = idx >> 4, c4 = idx & 15;
            *(float4*)&Ws[r][c4 * 4] =
                *(const float4*)(W + ((size_t)(k0 + r)) * 64 + c4 * 4);
        }
        __syncthreads();

#pragma unroll
        for (int kk = 0; kk < GBK; kk++) {
            float4 w4 = *(const float4*)&Ws[kk][tc * 4];
#pragma unroll
            for (int i = 0; i < 2; i++) {
                float a = As[tr * 2 + i][kk];
                acc[i][0] += a * w4.x;
                acc[i][1] += a * w4.y;
                acc[i][2] += a * w4.z;
                acc[i][3] += a * w4.w;
            }
        }
        __syncthreads();
    }

#pragma unroll
    for (int i = 0; i < 2; i++) {
        int r = row0 + tr * 2 + i;
        float4 o;
        o.x = acc[i][0] + bias[tc * 4 + 0];
        o.y = acc[i][1] + bias[tc * 4 + 1];
        o.z = acc[i][2] + bias[tc * 4 + 2];
        o.w = acc[i][3] + bias[tc * 4 + 3];
        *(float4*)(out + (size_t)r * 64 + tc * 4) = o;
    }
}

// ---------------------------------------------------------------------------
extern "C" void kernel_launch(void* const* d_in, const int* in_sizes, int n_in,
                              void* d_out, int out_size)
{
    const float* q    = (const float*)d_in[0];
    const float* k    = (const float*)d_in[1];
    const float* v    = (const float*)d_in[2];
    const float* Wout = (const float*)d_in[3];
    const float* bout = (const float*)d_in[4];
    float* out = (float*)d_out;

    static bool attr_set = false;
    if (!attr_set) {
        cudaFuncSetAttribute(attn_tc_kernel,
                             cudaFuncAttributeMaxDynamicSharedMemorySize, SMEM_BYTES);
        attr_set = true;
    }

    cvt_kernel<<<dim3(2048, 3), 256>>>(q, k, v);

    dim3 agrid(BATCH * NH, SEQ / BM);
    attn_tc_kernel<<<agrid, BM, SMEM_BYTES>>>();

    dim3 pgrid((BATCH * SEQ) / GBM);
    proj_kernel<<<pgrid, 256>>>(Wout, bout, out);
}